// round 8
// baseline (speedup 1.0000x reference)
#include <cuda_runtime.h>

// BoxFilterND: truncated 2D box SUM, radius 8, over dims 2,3 of (8,32,512,512) fp32.
// out[r][c] = sum_{dr=-8..8, dc=-8..8, in-bounds} in[r+dr][c+dc]
//
// Fused single pass (design frozen pending first measurement):
//   - vertical sliding-window sum per column (17-row shared FIFO ring, 1 cold LDG/elem,
//     next-batch loads prefetched into registers to overlap with horizontal phase)
//   - horizontal window: per 4-output tile, union of windows = 20 cols = 5 x LDS.128
//     from a zero-padded vertical-sum row buffer; register sliding window; STG.128 out.
//   - cache policy: main-loop input streams once (__ldcs), output write-once (__stcs);
//     prologue rows use default caching (they are the cross-chunk L2-reuse set).
// Grid: 256 planes x 2 row-chunks of 256 rows (single resident wave at occ 4/SM).
// Block: 512 threads.

#define NP    512      // rows per plane
#define W     512      // cols per plane
#define RAD   8
#define WIN   17       // 2*RAD+1
#define CHUNK 256      // output rows per CTA
#define RB    4        // rows per batch
#define VB    528      // padded vertical-sum row: 8 + 512 + 8  (16B-aligned stride)

__global__ __launch_bounds__(512)
void boxfilter2d_kernel(const float* __restrict__ in, float* __restrict__ out) {
    __shared__ float ring[WIN][W];                // last 17 input rows (thread-private cols)
    __shared__ __align__(16) float vbuf[RB][VB];  // vertical sums, zero-padded +-8

    const int c     = threadIdx.x;
    const int plane = blockIdx.x >> 1;
    const int chunk = blockIdx.x & 1;
    const int r0    = chunk * CHUNK;

    const float* __restrict__ pin  = in  + (size_t)plane * (NP * W);
    float*       __restrict__ pout = out + (size_t)plane * (NP * W);

    // Horizontal-pass role: group g handles row (rb+g), 128 threads * 4 cols each.
    const int g  = c >> 7;          // 0..3
    const int tt = c & 127;         // 0..127 -> output cols 4*tt .. 4*tt+3

    // Zero the pads once (never overwritten; vertical writes only [8..519]).
    if (c < 8) {
        #pragma unroll
        for (int rr = 0; rr < RB; ++rr) {
            vbuf[rr][c]       = 0.f;
            vbuf[rr][520 + c] = 0.f;
        }
    }

    // ---- Prologue: rows [r0-9, r0+7] into FIFO slots 0..16; sv = their sum.
    // Invariant before output row r: sv = sum of rows [r-9, r+7] (zeros out of range).
    float sv = 0.f;
    #pragma unroll
    for (int i = 0; i < WIN; ++i) {
        int k = r0 - (RAD + 1) + i;               // k <= r0+7 <= 263 < 512 always
        float v = (k >= 0) ? __ldg(&pin[k * W + c]) : 0.f;
        ring[i][c] = v;
        sv += v;
    }
    int slot = 0;   // slot of the trailing row (r-9) for the first output row r0

    // Prefetch first batch's leading rows (r0+8 .. r0+11) into registers.
    float nv[RB];
    #pragma unroll
    for (int rr = 0; rr < RB; ++rr) {
        int L = r0 + rr + RAD;
        nv[rr] = (L < NP) ? __ldcs(&pin[L * W + c]) : 0.f;
    }

    for (int rb = 0; rb < CHUNK; rb += RB) {
        // ---- Vertical sliding updates for RB rows (column-private, no hazards)
        #pragma unroll
        for (int rr = 0; rr < RB; ++rr) {
            float oldv = ring[slot][c];           // trailing row r-9
            sv += nv[rr] - oldv;
            ring[slot][c] = nv[rr];
            slot = (slot == WIN - 1) ? 0 : slot + 1;
            vbuf[rr][RAD + c] = sv;               // vertical box sum for this row, col c
        }

        // ---- Prefetch NEXT batch's leading rows; loads fly during barrier+horizontal.
        #pragma unroll
        for (int rr = 0; rr < RB; ++rr) {
            int L = r0 + rb + RB + rr + RAD;
            nv[rr] = (L < NP) ? __ldcs(&pin[L * W + c]) : 0.f;
        }
        __syncthreads();

        // ---- Horizontal: 4 outputs per thread from 20 contiguous vertical sums.
        // Window union for outputs 4tt..4tt+3 is cols [4tt-8, 4tt+11]
        //   = vbuf indices [4tt, 4tt+19] -> 5 aligned float4 loads.
        {
            const float4* vp = (const float4*)&vbuf[g][4 * tt];
            float4 A = vp[0], B = vp[1], C = vp[2], D = vp[3], E = vp[4];
            float x0=A.x,x1=A.y,x2=A.z,x3=A.w, x4=B.x,x5=B.y,x6=B.z,x7=B.w;
            float x8=C.x,x9=C.y,x10=C.z,x11=C.w, x12=D.x,x13=D.y,x14=D.z,x15=D.w;
            float x16=E.x,x17=E.y,x18=E.z,x19=E.w;

            float s0 = ((x0+x1)+(x2+x3)) + ((x4+x5)+(x6+x7))
                     + ((x8+x9)+(x10+x11)) + ((x12+x13)+(x14+x15)) + x16;
            float s1 = s0 - x0 + x17;
            float s2 = s1 - x1 + x18;
            float s3 = s2 - x2 + x19;

            float4 o; o.x = s0; o.y = s1; o.z = s2; o.w = s3;
            __stcs((float4*)&pout[(size_t)(r0 + rb + g) * W + 4 * tt], o);
        }
        __syncthreads();   // vbuf consumed before next batch overwrites it
    }
}

extern "C" void kernel_launch(void* const* d_in, const int* in_sizes, int n_in,
                              void* d_out, int out_size) {
    const float* in = (const float*)d_in[0];
    float* out = (float*)d_out;
    // 8*32 = 256 planes, 2 row-chunks each
    boxfilter2d_kernel<<<512, 512>>>(in, out);
}